// round 1
// baseline (speedup 1.0000x reference)
#include <cuda_runtime.h>
#include <math.h>

// Problem constants
#define BB 2
#define TT 2048
#define EMB 1024
#define HEADS 16
#define HS 64
#define NROWS (BB*TT)          // 4096

// Scratch (allocation-free rule: __device__ globals)
__device__ float g_q[(size_t)BB*HEADS*TT*HS];     // [b*16+h][t][d]
__device__ float g_k[(size_t)BB*HEADS*TT*HS];
__device__ float g_v[(size_t)BB*HEADS*TT*HS];
__device__ float g_attn[(size_t)NROWS*EMB];       // [b*T+t][h*64+d]

// ---------------------------------------------------------------------------
// SGEMM: C[M,N] = A[M,K] * B[K,N]  (row-major), BM=BN=128, BK=16, 256 thr, 8x8
// EPI=0: scatter into g_q/g_k/g_v   EPI=1: +bias, write to out
// ---------------------------------------------------------------------------
template<int EPI>
__global__ __launch_bounds__(256, 2)
void sgemm128(const float* __restrict__ A, const float* __restrict__ Bm,
              const float* __restrict__ bias, float* __restrict__ Cout,
              int M, int N, int K)
{
    __shared__ float As[16][132];   // transposed A tile, padded (2-way max)
    __shared__ float Bs[16][128];

    const int tid = threadIdx.x;
    const int bx = blockIdx.x;      // N tile
    const int by = blockIdx.y;      // M tile

    const int tr = tid >> 4;        // 0..15
    const int tc = tid & 15;        // 0..15

    // A loader: float4 at (rowA [+64], colA4*4)
    const int rowA = tid >> 2;      // 0..63
    const int colA4 = tid & 3;      // 0..3
    // B loader: float4 at (rowB [+8], colB4*4)
    const int rowB = tid >> 5;      // 0..7
    const int colB4 = tid & 31;     // 0..31

    const float* Ap = (EPI == 1) ? g_attn : A;
    const float* Abase = Ap + (size_t)(by * 128) * K;
    const float* Bbase = Bm + bx * 128;

    // initial global fetch (k-tile 0)
    float4 a0 = *(const float4*)(Abase + (size_t)rowA * K + colA4 * 4);
    float4 a1 = *(const float4*)(Abase + (size_t)(rowA + 64) * K + colA4 * 4);
    float4 b0 = *(const float4*)(Bbase + (size_t)rowB * N + colB4 * 4);
    float4 b1 = *(const float4*)(Bbase + (size_t)(rowB + 8) * N + colB4 * 4);

    float acc[8][8];
    #pragma unroll
    for (int i = 0; i < 8; i++)
        #pragma unroll
        for (int j = 0; j < 8; j++) acc[i][j] = 0.f;

    const int nk = K >> 4;
    for (int kt = 0; kt < nk; kt++) {
        // stage registers -> smem (A transposed)
        As[colA4*4+0][rowA] = a0.x;  As[colA4*4+1][rowA] = a0.y;
        As[colA4*4+2][rowA] = a0.z;  As[colA4*4+3][rowA] = a0.w;
        As[colA4*4+0][rowA+64] = a1.x;  As[colA4*4+1][rowA+64] = a1.y;
        As[colA4*4+2][rowA+64] = a1.z;  As[colA4*4+3][rowA+64] = a1.w;
        *(float4*)&Bs[rowB][colB4*4]   = b0;
        *(float4*)&Bs[rowB+8][colB4*4] = b1;
        __syncthreads();

        // prefetch next k-tile while computing
        if (kt + 1 < nk) {
            const float* An = Abase + (kt + 1) * 16;
            const float* Bn = Bbase + (size_t)(kt + 1) * 16 * N;
            a0 = *(const float4*)(An + (size_t)rowA * K + colA4 * 4);
            a1 = *(const float4*)(An + (size_t)(rowA + 64) * K + colA4 * 4);
            b0 = *(const float4*)(Bn + (size_t)rowB * N + colB4 * 4);
            b1 = *(const float4*)(Bn + (size_t)(rowB + 8) * N + colB4 * 4);
        }

        #pragma unroll
        for (int k = 0; k < 16; k++) {
            float4 m0 = *(const float4*)&As[k][tr*4];
            float4 m1 = *(const float4*)&As[k][64 + tr*4];
            float4 n0 = *(const float4*)&Bs[k][tc*4];
            float4 n1 = *(const float4*)&Bs[k][64 + tc*4];
            float rm[8] = {m0.x,m0.y,m0.z,m0.w, m1.x,m1.y,m1.z,m1.w};
            float rn[8] = {n0.x,n0.y,n0.z,n0.w, n1.x,n1.y,n1.z,n1.w};
            #pragma unroll
            for (int i = 0; i < 8; i++)
                #pragma unroll
                for (int j = 0; j < 8; j++)
                    acc[i][j] = fmaf(rm[i], rn[j], acc[i][j]);
        }
        __syncthreads();
    }

    // epilogue
    #pragma unroll
    for (int ih = 0; ih < 2; ih++) {
        #pragma unroll
        for (int ii = 0; ii < 4; ii++) {
            const int i = ih * 4 + ii;
            const int row = by * 128 + ih * 64 + tr * 4 + ii;
            #pragma unroll
            for (int jh = 0; jh < 2; jh++) {
                const int j = jh * 4;
                const int c0 = bx * 128 + jh * 64 + tc * 4;
                float4 v = make_float4(acc[i][j], acc[i][j+1], acc[i][j+2], acc[i][j+3]);
                if (EPI == 0) {
                    // scatter into q/k/v [b*16+h][t][d]
                    const int b = row >> 11, t = row & 2047;
                    const int mat = c0 >> 10, cc = c0 & 1023;
                    const int head = cc >> 6, d = cc & 63;
                    float* base = (mat == 0) ? g_q : ((mat == 1) ? g_k : g_v);
                    *(float4*)(base + (((size_t)(b * HEADS + head) * TT + t) * HS + d)) = v;
                } else {
                    float4 bv = *(const float4*)(bias + c0);
                    v.x += bv.x; v.y += bv.y; v.z += bv.z; v.w += bv.w;
                    *(float4*)(Cout + (size_t)row * N + c0) = v;
                }
            }
        }
    }
}

// ---------------------------------------------------------------------------
// Flash attention, fp32, causal. BM=BN=64, hs=64, 256 threads (16x16, 4x4).
// smem: Qs[64][64] | Ks_t[64][68] (K transposed) | Vs[64][64] | Ps[64][64]
// ---------------------------------------------------------------------------
#define KSTRIDE 68
#define ATT_SMEM_FLOATS (64*64 + 64*KSTRIDE + 64*64 + 64*64)   // 16640
#define ATT_SMEM_BYTES  (ATT_SMEM_FLOATS * 4)                  // 66560

__global__ __launch_bounds__(256, 3)
void attn_kernel()
{
    extern __shared__ float sm[];
    float* Qs = sm;                    // [r][d]  stride 64
    float* Ks = sm + 64 * 64;          // [d][c]  stride 68 (transposed)
    float* Vs = Ks + 64 * KSTRIDE;     // [c][d]  stride 64
    float* Ps = Vs + 64 * 64;          // [r][c]  stride 64

    const int tid = threadIdx.x;
    const int qt = gridDim.x - 1 - blockIdx.x;   // heavy tiles launch first
    const int bh = blockIdx.y;
    const int q0 = qt * 64;

    const float* Qg = g_q + ((size_t)bh * TT + q0) * HS;
    const float* Kg = g_k + (size_t)bh * TT * HS;
    const float* Vg = g_v + (size_t)bh * TT * HS;

    const int ty = tid >> 4;     // row group 0..15
    const int tx = tid & 15;     // col group 0..15

    // load Q tile (scaled by hs^-0.5 = 0.125)
    #pragma unroll
    for (int p = 0; p < 4; p++) {
        int f = tid + p * 256;            // float4 index 0..1023
        int r = f >> 4, d4 = f & 15;
        float4 v = *(const float4*)(Qg + r * 64 + d4 * 4);
        v.x *= 0.125f; v.y *= 0.125f; v.z *= 0.125f; v.w *= 0.125f;
        *(float4*)(Qs + r * 64 + d4 * 4) = v;
    }

    float m_i[4], l_i[4], o[4][4];
    #pragma unroll
    for (int i = 0; i < 4; i++) {
        m_i[i] = -1e30f; l_i[i] = 0.f;
        #pragma unroll
        for (int j = 0; j < 4; j++) o[i][j] = 0.f;
    }

    for (int kt = 0; kt <= qt; kt++) {
        __syncthreads();   // prior-iter Ps/Vs readers done before overwrite
        const float* Kt = Kg + (size_t)kt * 64 * 64;
        const float* Vt = Vg + (size_t)kt * 64 * 64;
        #pragma unroll
        for (int p = 0; p < 4; p++) {
            int f = tid + p * 256;
            int r = f >> 4, d4 = f & 15;
            float4 kv = *(const float4*)(Kt + r * 64 + d4 * 4);
            Ks[(d4*4+0) * KSTRIDE + r] = kv.x;
            Ks[(d4*4+1) * KSTRIDE + r] = kv.y;
            Ks[(d4*4+2) * KSTRIDE + r] = kv.z;
            Ks[(d4*4+3) * KSTRIDE + r] = kv.w;
            *(float4*)(Vs + r * 64 + d4 * 4) = *(const float4*)(Vt + r * 64 + d4 * 4);
        }
        __syncthreads();

        // S = Q K^T (4x4 microtile)
        float s[4][4];
        #pragma unroll
        for (int i = 0; i < 4; i++)
            #pragma unroll
            for (int j = 0; j < 4; j++) s[i][j] = 0.f;

        #pragma unroll 16
        for (int d = 0; d < 64; d++) {
            float4 kk = *(const float4*)(Ks + d * KSTRIDE + tx * 4);
            float rk[4] = {kk.x, kk.y, kk.z, kk.w};
            #pragma unroll
            for (int i = 0; i < 4; i++) {
                float qv = Qs[(ty * 4 + i) * 64 + d];
                #pragma unroll
                for (int j = 0; j < 4; j++)
                    s[i][j] = fmaf(qv, rk[j], s[i][j]);
            }
        }

        // causal mask on diagonal tile (local indices valid since tiles aligned)
        if (kt == qt) {
            #pragma unroll
            for (int i = 0; i < 4; i++)
                #pragma unroll
                for (int j = 0; j < 4; j++)
                    if ((tx * 4 + j) > (ty * 4 + i)) s[i][j] = -1e30f;
        }

        // online softmax per row (rows shared across the 16 tx lanes)
        #pragma unroll
        for (int i = 0; i < 4; i++) {
            float mx = fmaxf(fmaxf(s[i][0], s[i][1]), fmaxf(s[i][2], s[i][3]));
            #pragma unroll
            for (int off = 8; off >= 1; off >>= 1)
                mx = fmaxf(mx, __shfl_xor_sync(0xffffffffu, mx, off));
            float mnew = fmaxf(m_i[i], mx);
            float corr = __expf(m_i[i] - mnew);
            float rs = 0.f;
            #pragma unroll
            for (int j = 0; j < 4; j++) {
                s[i][j] = __expf(s[i][j] - mnew);
                rs += s[i][j];
            }
            #pragma unroll
            for (int off = 8; off >= 1; off >>= 1)
                rs += __shfl_xor_sync(0xffffffffu, rs, off);
            l_i[i] = l_i[i] * corr + rs;
            m_i[i] = mnew;
            #pragma unroll
            for (int j = 0; j < 4; j++) o[i][j] *= corr;
            *(float4*)(Ps + (ty * 4 + i) * 64 + tx * 4) =
                make_float4(s[i][0], s[i][1], s[i][2], s[i][3]);
        }
        __syncthreads();

        // O += P V
        #pragma unroll 16
        for (int k = 0; k < 64; k++) {
            float4 vv = *(const float4*)(Vs + k * 64 + tx * 4);
            float rv[4] = {vv.x, vv.y, vv.z, vv.w};
            #pragma unroll
            for (int i = 0; i < 4; i++) {
                float pv = Ps[(ty * 4 + i) * 64 + k];
                #pragma unroll
                for (int j = 0; j < 4; j++)
                    o[i][j] = fmaf(pv, rv[j], o[i][j]);
            }
        }
    }

    // write [b*T+t][h*64+d]
    const int h = bh & (HEADS - 1);
    const int b = bh >> 4;
    #pragma unroll
    for (int i = 0; i < 4; i++) {
        float inv = 1.0f / l_i[i];
        int r = q0 + ty * 4 + i;
        float4 ov = make_float4(o[i][0]*inv, o[i][1]*inv, o[i][2]*inv, o[i][3]*inv);
        *(float4*)(g_attn + ((size_t)(b * TT + r)) * EMB + h * HS + tx * 4) = ov;
    }
}

// ---------------------------------------------------------------------------
extern "C" void kernel_launch(void* const* d_in, const int* in_sizes, int n_in,
                              void* d_out, int out_size)
{
    const float* x      = (const float*)d_in[0];
    const float* w_qkv  = (const float*)d_in[1];
    const float* w_proj = (const float*)d_in[2];
    const float* b_proj = (const float*)d_in[3];
    float* out = (float*)d_out;

    cudaFuncSetAttribute(attn_kernel,
                         cudaFuncAttributeMaxDynamicSharedMemorySize,
                         ATT_SMEM_BYTES);

    // QKV projection: [4096,1024] x [1024,3072] -> scatter q/k/v
    sgemm128<0><<<dim3(3 * EMB / 128, NROWS / 128), 256>>>(
        x, w_qkv, nullptr, nullptr, NROWS, 3 * EMB, EMB);

    // causal flash attention over 32 (b,h) pairs
    attn_kernel<<<dim3(TT / 64, BB * HEADS), 256, ATT_SMEM_BYTES>>>();

    // output projection: [4096,1024] x [1024,1024] + bias -> out
    sgemm128<1><<<dim3(EMB / 128, NROWS / 128), 256>>>(
        nullptr, w_proj, b_proj, out, NROWS, EMB, EMB);
}

// round 4
// speedup vs baseline: 1.3490x; 1.3490x over previous
#include <cuda_runtime.h>
#include <cuda_bf16.h>
#include <cstdint>
#include <math.h>

// Problem constants
#define BB 2
#define TT 2048
#define EMB 1024
#define HEADS 16
#define HS 64
#define NROWS (BB*TT)          // 4096
#define GK 1024                // K for both GEMMs

// ---------------------------------------------------------------------------
// Scratch (__device__ globals; allocation-free rule)
// ---------------------------------------------------------------------------
__device__ float g_q[(size_t)BB*HEADS*TT*HS];
__device__ float g_k[(size_t)BB*HEADS*TT*HS];
__device__ float g_v[(size_t)BB*HEADS*TT*HS];
__device__ float g_attn[(size_t)NROWS*EMB];

__device__ __nv_bfloat16 g_xhi[(size_t)NROWS*GK];
__device__ __nv_bfloat16 g_xlo[(size_t)NROWS*GK];
__device__ __nv_bfloat16 g_ahi[(size_t)NROWS*GK];
__device__ __nv_bfloat16 g_alo[(size_t)NROWS*GK];
__device__ __nv_bfloat16 g_wqhi[(size_t)3*EMB*GK];   // [3072][1024] K-major
__device__ __nv_bfloat16 g_wqlo[(size_t)3*EMB*GK];
__device__ __nv_bfloat16 g_wphi[(size_t)EMB*GK];     // [1024][1024] K-major
__device__ __nv_bfloat16 g_wplo[(size_t)EMB*GK];

// ---------------------------------------------------------------------------
// PTX helpers (portable sm_80+ subset only: ldmatrix / mma.sync / cp.async)
// ---------------------------------------------------------------------------
__device__ __forceinline__ uint32_t smem_u32(const void* p) {
    uint32_t a;
    asm("{ .reg .u64 t; cvta.to.shared.u64 t, %1; cvt.u32.u64 %0, t; }" : "=r"(a) : "l"(p));
    return a;
}
__device__ __forceinline__ void cp16(uint32_t dst, const void* src) {
    asm volatile("cp.async.ca.shared.global [%0], [%1], 16;" :: "r"(dst), "l"(src));
}
__device__ __forceinline__ void cp_commit() {
    asm volatile("cp.async.commit_group;" ::: "memory");
}
template<int N>
__device__ __forceinline__ void cp_wait() {
    asm volatile("cp.async.wait_group %0;" :: "n"(N) : "memory");
}
__device__ __forceinline__ void ldsm4(uint32_t* r, uint32_t a) {
    asm volatile("ldmatrix.sync.aligned.m8n8.x4.shared.b16 {%0,%1,%2,%3}, [%4];"
        : "=r"(r[0]), "=r"(r[1]), "=r"(r[2]), "=r"(r[3]) : "r"(a));
}
// NON-trans x2: for [n][k]-stored B, gives lane l -> W[n=l/4][k=(l%4)*2+{0,1}]
// == col-major B fragment of mma.m16n8k16.  (R3 bug: had .trans here.)
__device__ __forceinline__ void ldsm2(uint32_t* r, uint32_t a) {
    asm volatile("ldmatrix.sync.aligned.m8n8.x2.shared.b16 {%0,%1}, [%2];"
        : "=r"(r[0]), "=r"(r[1]) : "r"(a));
}
__device__ __forceinline__ void mma16816(float* d, const uint32_t* a, const uint32_t* b) {
    asm volatile("mma.sync.aligned.m16n8k16.row.col.f32.bf16.bf16.f32 "
        "{%0,%1,%2,%3}, {%4,%5,%6,%7}, {%8,%9}, {%0,%1,%2,%3};"
        : "+f"(d[0]), "+f"(d[1]), "+f"(d[2]), "+f"(d[3])
        : "r"(a[0]), "r"(a[1]), "r"(a[2]), "r"(a[3]), "r"(b[0]), "r"(b[1]));
}

// ---------------------------------------------------------------------------
// fp32 -> bf16 hi/lo split
// ---------------------------------------------------------------------------
__global__ void split_fp32(const float4* __restrict__ src,
                           __nv_bfloat162* __restrict__ hi,
                           __nv_bfloat162* __restrict__ lo, int n4)
{
    int i = blockIdx.x * blockDim.x + threadIdx.x;
    if (i >= n4) return;
    float4 v = src[i];
    __nv_bfloat16 hx = __float2bfloat16(v.x), hy = __float2bfloat16(v.y);
    __nv_bfloat16 hz = __float2bfloat16(v.z), hw = __float2bfloat16(v.w);
    hi[2*i]   = __halves2bfloat162(hx, hy);
    hi[2*i+1] = __halves2bfloat162(hz, hw);
    lo[2*i]   = __halves2bfloat162(__float2bfloat16(v.x - __bfloat162float(hx)),
                                   __float2bfloat16(v.y - __bfloat162float(hy)));
    lo[2*i+1] = __halves2bfloat162(__float2bfloat16(v.z - __bfloat162float(hz)),
                                   __float2bfloat16(v.w - __bfloat162float(hw)));
}

// ---------------------------------------------------------------------------
// transpose + split: W [K=1024][N] fp32 -> hi/lo [N][K=1024] bf16
// ---------------------------------------------------------------------------
__global__ void tsplit_w(const float* __restrict__ src,
                         __nv_bfloat16* __restrict__ hi,
                         __nv_bfloat16* __restrict__ lo, int N)
{
    __shared__ float t[32][33];
    const int n0 = blockIdx.x * 32, k0 = blockIdx.y * 32;
    const int tx = threadIdx.x, ty = threadIdx.y;
    #pragma unroll
    for (int r = ty; r < 32; r += 8)
        t[r][tx] = src[(size_t)(k0 + r) * N + n0 + tx];
    __syncthreads();
    #pragma unroll
    for (int r = ty; r < 32; r += 8) {
        float v = t[tx][r];
        __nv_bfloat16 h = __float2bfloat16(v);
        size_t o = (size_t)(n0 + r) * GK + k0 + tx;
        hi[o] = h;
        lo[o] = __float2bfloat16(v - __bfloat162float(h));
    }
}

// ---------------------------------------------------------------------------
// HMMA GEMM: C[M,N] = A[M,1024] * B[N,1024]^T via bf16 split (3 mma terms)
// 128x128 tile, BK=32, 256 threads (8 warps, 2x4), cp.async double buffer.
// Smem rows padded to 40 elems (80B) -> conflict-free ldmatrix.
// EPI=0: scatter into g_q/g_k/g_v    EPI=1: +bias -> Cout
// ---------------------------------------------------------------------------
#define BK 32
#define AST 40                        // row stride in elems (80 bytes)
#define MATB (128 * AST * 2)          // 10240 B per matrix tile
#define STAGEB (4 * MATB)             // 40960 B (Ahi, Alo, Bhi, Blo)
#define GEMM_SMEM (2 * STAGEB)        // 81920 B

template<int EPI>
__global__ __launch_bounds__(256, 2)
void mma_gemm(const __nv_bfloat16* __restrict__ Ahi, const __nv_bfloat16* __restrict__ Alo,
              const __nv_bfloat16* __restrict__ Bhi, const __nv_bfloat16* __restrict__ Blo,
              const float* __restrict__ bias, float* __restrict__ Cout)
{
    extern __shared__ char smc[];
    const uint32_t sb = smem_u32(smc);

    const int tid = threadIdx.x;
    const int wid = tid >> 5, lane = tid & 31;
    const int warp_m = wid >> 2;      // 0..1
    const int warp_n = wid & 3;       // 0..3
    const int m0 = blockIdx.y * 128, n0 = blockIdx.x * 128;

    // async loader: 2048 16B chunks per stage, 8 per thread
    auto issue = [&](int kc, int s) {
        const uint32_t dstb = sb + s * STAGEB;
        #pragma unroll
        for (int i = 0; i < 8; i++) {
            int idx = i * 256 + tid;
            int mtx = idx >> 9;                 // 0:Ahi 1:Alo 2:Bhi 3:Blo
            int r   = (idx >> 2) & 127;
            int c4  = idx & 3;
            const __nv_bfloat16* p;
            if      (mtx == 0) p = Ahi + (size_t)(m0 + r) * GK;
            else if (mtx == 1) p = Alo + (size_t)(m0 + r) * GK;
            else if (mtx == 2) p = Bhi + (size_t)(n0 + r) * GK;
            else               p = Blo + (size_t)(n0 + r) * GK;
            p += kc * BK + c4 * 8;
            cp16(dstb + mtx * MATB + r * 80 + c4 * 16, p);
        }
        cp_commit();
    };

    float acc[4][4][4];
    #pragma unroll
    for (int a = 0; a < 4; a++)
        #pragma unroll
        for (int b = 0; b < 4; b++)
            #pragma unroll
            for (int c = 0; c < 4; c++) acc[a][b][c] = 0.f;

    issue(0, 0);
    const int NIT = GK / BK;            // 32
    for (int kc = 0; kc < NIT; kc++) {
        const int s = kc & 1;
        if (kc + 1 < NIT) { issue(kc + 1, s ^ 1); cp_wait<1>(); }
        else              { cp_wait<0>(); }
        __syncthreads();

        const uint32_t Ah = sb + s * STAGEB;
        const uint32_t Al = Ah + MATB;
        const uint32_t Bh = Ah + 2 * MATB;
        const uint32_t Bl = Ah + 3 * MATB;

        #pragma unroll
        for (int ks = 0; ks < 2; ks++) {
            const uint32_t kb = ks * 32 + (lane >> 4) * 16;       // A k-byte offset
            uint32_t ah[4][4], al[4][4];
            #pragma unroll
            for (int mt = 0; mt < 4; mt++) {
                uint32_t ro = (uint32_t)(warp_m * 64 + mt * 16 + (lane & 15)) * 80 + kb;
                ldsm4(ah[mt], Ah + ro);
                ldsm4(al[mt], Al + ro);
            }
            const uint32_t kbb = ks * 32 + ((lane >> 3) & 1) * 16; // B k-byte offset
            #pragma unroll
            for (int nt = 0; nt < 4; nt++) {
                uint32_t ro = (uint32_t)(warp_n * 32 + nt * 8 + (lane & 7)) * 80 + kbb;
                uint32_t bh[2], bl[2];
                ldsm2(bh, Bh + ro);
                ldsm2(bl, Bl + ro);
                #pragma unroll
                for (int mt = 0; mt < 4; mt++) {
                    mma16816(acc[mt][nt], ah[mt], bh);
                    mma16816(acc[mt][nt], al[mt], bh);
                    mma16816(acc[mt][nt], ah[mt], bl);
                }
            }
        }
        __syncthreads();
    }

    // epilogue: lane l holds rows {g, g+8}, cols {tg*2, tg*2+1} per 16x8 tile
    const int g = lane >> 2, tg = lane & 3;
    #pragma unroll
    for (int mt = 0; mt < 4; mt++) {
        #pragma unroll
        for (int nt = 0; nt < 4; nt++) {
            const int c  = n0 + warp_n * 32 + nt * 8 + tg * 2;
            const int r0 = m0 + warp_m * 64 + mt * 16 + g;
            #pragma unroll
            for (int h = 0; h < 2; h++) {
                const int r = r0 + h * 8;
                float2 v = make_float2(acc[mt][nt][2*h], acc[mt][nt][2*h+1]);
                if (EPI == 0) {
                    const int bb = r >> 11, t = r & 2047;
                    const int mat = c >> 10, cc = c & 1023;
                    const int head = cc >> 6, d = cc & 63;
                    float* basep = (mat == 0) ? g_q : ((mat == 1) ? g_k : g_v);
                    *(float2*)(basep + (((size_t)(bb * HEADS + head) * TT + t) * HS + d)) = v;
                } else {
                    float2 bv = *(const float2*)(bias + c);
                    v.x += bv.x; v.y += bv.y;
                    *(float2*)(Cout + (size_t)r * EMB + c) = v;
                }
            }
        }
    }
}

// ---------------------------------------------------------------------------
// Flash attention, fp32, causal. BM=BN=64, hs=64, 256 threads (16x16, 4x4).
// (unchanged — R1-validated)
// ---------------------------------------------------------------------------
#define KSTRIDE 68
#define ATT_SMEM_FLOATS (64*64 + 64*KSTRIDE + 64*64 + 64*64)
#define ATT_SMEM_BYTES  (ATT_SMEM_FLOATS * 4)

__global__ __launch_bounds__(256, 3)
void attn_kernel()
{
    extern __shared__ float smf[];
    float* Qs = smf;
    float* Ks = smf + 64 * 64;
    float* Vs = Ks + 64 * KSTRIDE;
    float* Ps = Vs + 64 * 64;

    const int tid = threadIdx.x;
    const int qt = gridDim.x - 1 - blockIdx.x;
    const int bh = blockIdx.y;
    const int q0 = qt * 64;

    const float* Qg = g_q + ((size_t)bh * TT + q0) * HS;
    const float* Kg = g_k + (size_t)bh * TT * HS;
    const float* Vg = g_v + (size_t)bh * TT * HS;

    const int ty = tid >> 4;
    const int tx = tid & 15;

    #pragma unroll
    for (int p = 0; p < 4; p++) {
        int f = tid + p * 256;
        int r = f >> 4, d4 = f & 15;
        float4 v = *(const float4*)(Qg + r * 64 + d4 * 4);
        v.x *= 0.125f; v.y *= 0.125f; v.z *= 0.125f; v.w *= 0.125f;
        *(float4*)(Qs + r * 64 + d4 * 4) = v;
    }

    float m_i[4], l_i[4], o[4][4];
    #pragma unroll
    for (int i = 0; i < 4; i++) {
        m_i[i] = -1e30f; l_i[i] = 0.f;
        #pragma unroll
        for (int j = 0; j < 4; j++) o[i][j] = 0.f;
    }

    for (int kt = 0; kt <= qt; kt++) {
        __syncthreads();
        const float* Kt = Kg + (size_t)kt * 64 * 64;
        const float* Vt = Vg + (size_t)kt * 64 * 64;
        #pragma unroll
        for (int p = 0; p < 4; p++) {
            int f = tid + p * 256;
            int r = f >> 4, d4 = f & 15;
            float4 kv = *(const float4*)(Kt + r * 64 + d4 * 4);
            Ks[(d4*4+0) * KSTRIDE + r] = kv.x;
            Ks[(d4*4+1) * KSTRIDE + r] = kv.y;
            Ks[(d4*4+2) * KSTRIDE + r] = kv.z;
            Ks[(d4*4+3) * KSTRIDE + r] = kv.w;
            *(float4*)(Vs + r * 64 + d4 * 4) = *(const float4*)(Vt + r * 64 + d4 * 4);
        }
        __syncthreads();

        float s[4][4];
        #pragma unroll
        for (int i = 0; i < 4; i++)
            #pragma unroll
            for (int j = 0; j < 4; j++) s[i][j] = 0.f;

        #pragma unroll 16
        for (int d = 0; d < 64; d++) {
            float4 kk = *(const float4*)(Ks + d * KSTRIDE + tx * 4);
            float rk[4] = {kk.x, kk.y, kk.z, kk.w};
            #pragma unroll
            for (int i = 0; i < 4; i++) {
                float qv = Qs[(ty * 4 + i) * 64 + d];
                #pragma unroll
                for (int j = 0; j < 4; j++)
                    s[i][j] = fmaf(qv, rk[j], s[i][j]);
            }
        }

        if (kt == qt) {
            #pragma unroll
            for (int i = 0; i < 4; i++)
                #pragma unroll
                for (int j = 0; j < 4; j++)
                    if ((tx * 4 + j) > (ty * 4 + i)) s[i][j] = -1e30f;
        }

        #pragma unroll
        for (int i = 0; i < 4; i++) {
            float mx = fmaxf(fmaxf(s[i][0], s[i][1]), fmaxf(s[i][2], s[i][3]));
            #pragma unroll
            for (int off = 8; off >= 1; off >>= 1)
                mx = fmaxf(mx, __shfl_xor_sync(0xffffffffu, mx, off));
            float mnew = fmaxf(m_i[i], mx);
            float corr = __expf(m_i[i] - mnew);
            float rs = 0.f;
            #pragma unroll
            for (int j = 0; j < 4; j++) {
                s[i][j] = __expf(s[i][j] - mnew);
                rs += s[i][j];
            }
            #pragma unroll
            for (int off = 8; off >= 1; off >>= 1)
                rs += __shfl_xor_sync(0xffffffffu, rs, off);
            l_i[i] = l_i[i] * corr + rs;
            m_i[i] = mnew;
            #pragma unroll
            for (int j = 0; j < 4; j++) o[i][j] *= corr;
            *(float4*)(Ps + (ty * 4 + i) * 64 + tx * 4) =
                make_float4(s[i][0], s[i][1], s[i][2], s[i][3]);
        }
        __syncthreads();

        #pragma unroll 16
        for (int k = 0; k < 64; k++) {
            float4 vv = *(const float4*)(Vs + k * 64 + tx * 4);
            float rv[4] = {vv.x, vv.y, vv.z, vv.w};
            #pragma unroll
            for (int i = 0; i < 4; i++) {
                float pv = Ps[(ty * 4 + i) * 64 + k];
                #pragma unroll
                for (int j = 0; j < 4; j++)
                    o[i][j] = fmaf(pv, rv[j], o[i][j]);
            }
        }
    }

    const int h = bh & (HEADS - 1);
    const int b = bh >> 4;
    #pragma unroll
    for (int i = 0; i < 4; i++) {
        float inv = 1.0f / l_i[i];
        int r = q0 + ty * 4 + i;
        float4 ov = make_float4(o[i][0]*inv, o[i][1]*inv, o[i][2]*inv, o[i][3]*inv);
        *(float4*)(g_attn + ((size_t)(b * TT + r)) * EMB + h * HS + tx * 4) = ov;
    }
}

// ---------------------------------------------------------------------------
extern "C" void kernel_launch(void* const* d_in, const int* in_sizes, int n_in,
                              void* d_out, int out_size)
{
    const float* x      = (const float*)d_in[0];
    const float* w_qkv  = (const float*)d_in[1];
    const float* w_proj = (const float*)d_in[2];
    const float* b_proj = (const float*)d_in[3];
    float* out = (float*)d_out;

    cudaFuncSetAttribute(attn_kernel, cudaFuncAttributeMaxDynamicSharedMemorySize, ATT_SMEM_BYTES);
    cudaFuncSetAttribute(mma_gemm<0>, cudaFuncAttributeMaxDynamicSharedMemorySize, GEMM_SMEM);
    cudaFuncSetAttribute(mma_gemm<1>, cudaFuncAttributeMaxDynamicSharedMemorySize, GEMM_SMEM);

    __nv_bfloat16 *xhi, *xlo, *ahi, *alo, *wqhi, *wqlo, *wphi, *wplo;
    cudaGetSymbolAddress((void**)&xhi,  g_xhi);
    cudaGetSymbolAddress((void**)&xlo,  g_xlo);
    cudaGetSymbolAddress((void**)&ahi,  g_ahi);
    cudaGetSymbolAddress((void**)&alo,  g_alo);
    cudaGetSymbolAddress((void**)&wqhi, g_wqhi);
    cudaGetSymbolAddress((void**)&wqlo, g_wqlo);
    cudaGetSymbolAddress((void**)&wphi, g_wphi);
    cudaGetSymbolAddress((void**)&wplo, g_wplo);
    float* attnp;
    cudaGetSymbolAddress((void**)&attnp, g_attn);

    // 1. split x -> bf16 hi/lo
    split_fp32<<<(NROWS * GK / 4 + 255) / 256, 256>>>(
        (const float4*)x, (__nv_bfloat162*)xhi, (__nv_bfloat162*)xlo, NROWS * GK / 4);

    // 2. transpose+split weights
    tsplit_w<<<dim3(3 * EMB / 32, GK / 32), dim3(32, 8)>>>(w_qkv, wqhi, wqlo, 3 * EMB);
    tsplit_w<<<dim3(EMB / 32, GK / 32), dim3(32, 8)>>>(w_proj, wphi, wplo, EMB);

    // 3. QKV GEMM (HMMA) -> scatter q/k/v
    mma_gemm<0><<<dim3(3 * EMB / 128, NROWS / 128), 256, GEMM_SMEM>>>(
        xhi, xlo, wqhi, wqlo, nullptr, nullptr);

    // 4. causal flash attention
    attn_kernel<<<dim3(TT / 64, BB * HEADS), 256, ATT_SMEM_BYTES>>>();

    // 5. split attention output
    split_fp32<<<(NROWS * GK / 4 + 255) / 256, 256>>>(
        (const float4*)attnp, (__nv_bfloat162*)ahi, (__nv_bfloat162*)alo, NROWS * GK / 4);

    // 6. output projection (HMMA) + bias
    mma_gemm<1><<<dim3(EMB / 128, NROWS / 128), 256, GEMM_SMEM>>>(
        ahi, alo, wphi, wplo, b_proj, out);
}

// round 5
// speedup vs baseline: 2.2950x; 1.7013x over previous
#include <cuda_runtime.h>
#include <cuda_bf16.h>
#include <cstdint>
#include <math.h>

// Problem constants
#define BB 2
#define TT 2048
#define EMB 1024
#define HEADS 16
#define HS 64
#define NROWS (BB*TT)          // 4096
#define GK 1024                // K for both GEMMs

// ---------------------------------------------------------------------------
// Scratch (__device__ globals; allocation-free rule)
// ---------------------------------------------------------------------------
__device__ __nv_bfloat16 g_qhi[(size_t)BB*HEADS*TT*HS];  // [bh][t][d], pre-scaled 0.125
__device__ __nv_bfloat16 g_qlo[(size_t)BB*HEADS*TT*HS];
__device__ __nv_bfloat16 g_khi[(size_t)BB*HEADS*TT*HS];
__device__ __nv_bfloat16 g_klo[(size_t)BB*HEADS*TT*HS];
__device__ __nv_bfloat16 g_vhi[(size_t)BB*HEADS*TT*HS];
__device__ __nv_bfloat16 g_vlo[(size_t)BB*HEADS*TT*HS];

__device__ __nv_bfloat16 g_xhi[(size_t)NROWS*GK];
__device__ __nv_bfloat16 g_xlo[(size_t)NROWS*GK];
__device__ __nv_bfloat16 g_ahi[(size_t)NROWS*GK];        // attention out (proj input)
__device__ __nv_bfloat16 g_alo[(size_t)NROWS*GK];
__device__ __nv_bfloat16 g_wqhi[(size_t)3*EMB*GK];       // [3072][1024] K-major
__device__ __nv_bfloat16 g_wqlo[(size_t)3*EMB*GK];
__device__ __nv_bfloat16 g_wphi[(size_t)EMB*GK];         // [1024][1024] K-major
__device__ __nv_bfloat16 g_wplo[(size_t)EMB*GK];

// ---------------------------------------------------------------------------
// PTX helpers (portable sm_80+ subset: ldmatrix / mma.sync / cp.async)
// ---------------------------------------------------------------------------
__device__ __forceinline__ uint32_t smem_u32(const void* p) {
    uint32_t a;
    asm("{ .reg .u64 t; cvta.to.shared.u64 t, %1; cvt.u32.u64 %0, t; }" : "=r"(a) : "l"(p));
    return a;
}
__device__ __forceinline__ void cp16(uint32_t dst, const void* src) {
    asm volatile("cp.async.ca.shared.global [%0], [%1], 16;" :: "r"(dst), "l"(src));
}
__device__ __forceinline__ void cp_commit() {
    asm volatile("cp.async.commit_group;" ::: "memory");
}
template<int N>
__device__ __forceinline__ void cp_wait() {
    asm volatile("cp.async.wait_group %0;" :: "n"(N) : "memory");
}
__device__ __forceinline__ void ldsm4(uint32_t* r, uint32_t a) {
    asm volatile("ldmatrix.sync.aligned.m8n8.x4.shared.b16 {%0,%1,%2,%3}, [%4];"
        : "=r"(r[0]), "=r"(r[1]), "=r"(r[2]), "=r"(r[3]) : "r"(a));
}
// non-trans x2: for [n][k]-stored rows -> col-major B fragment (R4-validated)
__device__ __forceinline__ void ldsm2(uint32_t* r, uint32_t a) {
    asm volatile("ldmatrix.sync.aligned.m8n8.x2.shared.b16 {%0,%1}, [%2];"
        : "=r"(r[0]), "=r"(r[1]) : "r"(a));
}
// trans x2: for [k][n]-stored rows (V tile) -> col-major B fragment
__device__ __forceinline__ void ldsm2t(uint32_t* r, uint32_t a) {
    asm volatile("ldmatrix.sync.aligned.m8n8.x2.trans.shared.b16 {%0,%1}, [%2];"
        : "=r"(r[0]), "=r"(r[1]) : "r"(a));
}
__device__ __forceinline__ void mma16816(float* d, const uint32_t* a, const uint32_t* b) {
    asm volatile("mma.sync.aligned.m16n8k16.row.col.f32.bf16.bf16.f32 "
        "{%0,%1,%2,%3}, {%4,%5,%6,%7}, {%8,%9}, {%0,%1,%2,%3};"
        : "+f"(d[0]), "+f"(d[1]), "+f"(d[2]), "+f"(d[3])
        : "r"(a[0]), "r"(a[1]), "r"(a[2]), "r"(a[3]), "r"(b[0]), "r"(b[1]));
}
__device__ __forceinline__ uint32_t packbf2(float a, float b) {
    __nv_bfloat162 h;
    h.x = __float2bfloat16(a); h.y = __float2bfloat16(b);
    return *(uint32_t*)&h;
}

// ---------------------------------------------------------------------------
// fp32 -> bf16 hi/lo split
// ---------------------------------------------------------------------------
__global__ void split_fp32(const float4* __restrict__ src,
                           __nv_bfloat162* __restrict__ hi,
                           __nv_bfloat162* __restrict__ lo, int n4)
{
    int i = blockIdx.x * blockDim.x + threadIdx.x;
    if (i >= n4) return;
    float4 v = src[i];
    __nv_bfloat16 hx = __float2bfloat16(v.x), hy = __float2bfloat16(v.y);
    __nv_bfloat16 hz = __float2bfloat16(v.z), hw = __float2bfloat16(v.w);
    hi[2*i]   = __halves2bfloat162(hx, hy);
    hi[2*i+1] = __halves2bfloat162(hz, hw);
    lo[2*i]   = __halves2bfloat162(__float2bfloat16(v.x - __bfloat162float(hx)),
                                   __float2bfloat16(v.y - __bfloat162float(hy)));
    lo[2*i+1] = __halves2bfloat162(__float2bfloat16(v.z - __bfloat162float(hz)),
                                   __float2bfloat16(v.w - __bfloat162float(hw)));
}

// ---------------------------------------------------------------------------
// transpose + split: W [K=1024][N] fp32 -> hi/lo [N][K=1024] bf16
// ---------------------------------------------------------------------------
__global__ void tsplit_w(const float* __restrict__ src,
                         __nv_bfloat16* __restrict__ hi,
                         __nv_bfloat16* __restrict__ lo, int N)
{
    __shared__ float t[32][33];
    const int n0 = blockIdx.x * 32, k0 = blockIdx.y * 32;
    const int tx = threadIdx.x, ty = threadIdx.y;
    #pragma unroll
    for (int r = ty; r < 32; r += 8)
        t[r][tx] = src[(size_t)(k0 + r) * N + n0 + tx];
    __syncthreads();
    #pragma unroll
    for (int r = ty; r < 32; r += 8) {
        float v = t[tx][r];
        __nv_bfloat16 h = __float2bfloat16(v);
        size_t o = (size_t)(n0 + r) * GK + k0 + tx;
        hi[o] = h;
        lo[o] = __float2bfloat16(v - __bfloat162float(h));
    }
}

// ---------------------------------------------------------------------------
// HMMA GEMM (R4-validated): C = A[M,1024] * B[N,1024]^T via bf16 split
// EPI=0: split + scatter into g_{q,k,v}{hi,lo} (Q scaled 0.125)
// EPI=1: +bias -> Cout (fp32)
// ---------------------------------------------------------------------------
#define BK 32
#define MATB (128 * 40 * 2)           // 10240 B per matrix tile (80B rows)
#define STAGEB (4 * MATB)
#define GEMM_SMEM (2 * STAGEB)

template<int EPI>
__global__ __launch_bounds__(256, 2)
void mma_gemm(const __nv_bfloat16* __restrict__ Ahi, const __nv_bfloat16* __restrict__ Alo,
              const __nv_bfloat16* __restrict__ Bhi, const __nv_bfloat16* __restrict__ Blo,
              const float* __restrict__ bias, float* __restrict__ Cout)
{
    extern __shared__ char smc[];
    const uint32_t sb = smem_u32(smc);

    const int tid = threadIdx.x;
    const int wid = tid >> 5, lane = tid & 31;
    const int warp_m = wid >> 2;
    const int warp_n = wid & 3;
    const int m0 = blockIdx.y * 128, n0 = blockIdx.x * 128;

    auto issue = [&](int kc, int s) {
        const uint32_t dstb = sb + s * STAGEB;
        #pragma unroll
        for (int i = 0; i < 8; i++) {
            int idx = i * 256 + tid;
            int mtx = idx >> 9;
            int r   = (idx >> 2) & 127;
            int c4  = idx & 3;
            const __nv_bfloat16* p;
            if      (mtx == 0) p = Ahi + (size_t)(m0 + r) * GK;
            else if (mtx == 1) p = Alo + (size_t)(m0 + r) * GK;
            else if (mtx == 2) p = Bhi + (size_t)(n0 + r) * GK;
            else               p = Blo + (size_t)(n0 + r) * GK;
            p += kc * BK + c4 * 8;
            cp16(dstb + mtx * MATB + r * 80 + c4 * 16, p);
        }
        cp_commit();
    };

    float acc[4][4][4];
    #pragma unroll
    for (int a = 0; a < 4; a++)
        #pragma unroll
        for (int b = 0; b < 4; b++)
            #pragma unroll
            for (int c = 0; c < 4; c++) acc[a][b][c] = 0.f;

    issue(0, 0);
    const int NIT = GK / BK;
    for (int kc = 0; kc < NIT; kc++) {
        const int s = kc & 1;
        if (kc + 1 < NIT) { issue(kc + 1, s ^ 1); cp_wait<1>(); }
        else              { cp_wait<0>(); }
        __syncthreads();

        const uint32_t Ah = sb + s * STAGEB;
        const uint32_t Al = Ah + MATB;
        const uint32_t Bh = Ah + 2 * MATB;
        const uint32_t Bl = Ah + 3 * MATB;

        #pragma unroll
        for (int ks = 0; ks < 2; ks++) {
            const uint32_t kb = ks * 32 + (lane >> 4) * 16;
            uint32_t ah[4][4], al[4][4];
            #pragma unroll
            for (int mt = 0; mt < 4; mt++) {
                uint32_t ro = (uint32_t)(warp_m * 64 + mt * 16 + (lane & 15)) * 80 + kb;
                ldsm4(ah[mt], Ah + ro);
                ldsm4(al[mt], Al + ro);
            }
            const uint32_t kbb = ks * 32 + ((lane >> 3) & 1) * 16;
            #pragma unroll
            for (int nt = 0; nt < 4; nt++) {
                uint32_t ro = (uint32_t)(warp_n * 32 + nt * 8 + (lane & 7)) * 80 + kbb;
                uint32_t bh[2], bl[2];
                ldsm2(bh, Bh + ro);
                ldsm2(bl, Bl + ro);
                #pragma unroll
                for (int mt = 0; mt < 4; mt++) {
                    mma16816(acc[mt][nt], ah[mt], bh);
                    mma16816(acc[mt][nt], al[mt], bh);
                    mma16816(acc[mt][nt], ah[mt], bl);
                }
            }
        }
        __syncthreads();
    }

    const int g = lane >> 2, tg = lane & 3;
    #pragma unroll
    for (int mt = 0; mt < 4; mt++) {
        #pragma unroll
        for (int nt = 0; nt < 4; nt++) {
            const int c  = n0 + warp_n * 32 + nt * 8 + tg * 2;
            const int r0 = m0 + warp_m * 64 + mt * 16 + g;
            #pragma unroll
            for (int h = 0; h < 2; h++) {
                const int r = r0 + h * 8;
                float2 v = make_float2(acc[mt][nt][2*h], acc[mt][nt][2*h+1]);
                if (EPI == 0) {
                    const int bb = r >> 11, t = r & 2047;
                    const int mat = c >> 10, cc = c & 1023;
                    const int head = cc >> 6, d = cc & 63;
                    if (mat == 0) { v.x *= 0.125f; v.y *= 0.125f; }
                    __nv_bfloat16 h0 = __float2bfloat16(v.x), h1 = __float2bfloat16(v.y);
                    __nv_bfloat162 hi2; hi2.x = h0; hi2.y = h1;
                    __nv_bfloat162 lo2;
                    lo2.x = __float2bfloat16(v.x - __bfloat162float(h0));
                    lo2.y = __float2bfloat16(v.y - __bfloat162float(h1));
                    size_t o = (((size_t)(bb * HEADS + head) * TT + t) * HS + d) >> 1;
                    __nv_bfloat162* hp = (mat == 0) ? (__nv_bfloat162*)g_qhi
                                        : (mat == 1) ? (__nv_bfloat162*)g_khi
                                                     : (__nv_bfloat162*)g_vhi;
                    __nv_bfloat162* lp = (mat == 0) ? (__nv_bfloat162*)g_qlo
                                        : (mat == 1) ? (__nv_bfloat162*)g_klo
                                                     : (__nv_bfloat162*)g_vlo;
                    hp[o] = hi2; lp[o] = lo2;
                } else {
                    float2 bv = *(const float2*)(bias + c);
                    v.x += bv.x; v.y += bv.y;
                    *(float2*)(Cout + (size_t)r * EMB + c) = v;
                }
            }
        }
    }
}

// ---------------------------------------------------------------------------
// Tensor-core flash attention. BM=128, BN=64, hs=64, 8 warps (16 rows each).
// Q fragments in registers; K/V hi/lo double-buffered cp.async (144B stride).
// 3-term bf16 split for both QK^T and PV. Causal per-warp tile classification.
// ---------------------------------------------------------------------------
#define ATILE_B  (64 * 144)            // 9216 B per 64-row tile
#define ASTAGE_B (4 * ATILE_B)         // Khi,Klo,Vhi,Vlo = 36864
#define ATT_SMEM (2 * ASTAGE_B)        // 73728

__global__ __launch_bounds__(256)
void attn_mma()
{
    extern __shared__ char sm[];
    const uint32_t sb = smem_u32(sm);
    const int tid = threadIdx.x, wid = tid >> 5, lane = tid & 31;
    const int qt = gridDim.x - 1 - blockIdx.x;     // heavy tiles first
    const int bh = blockIdx.y;
    const int q0 = qt * 128;
    const int g = lane >> 2, tg = lane & 3;

    // ---- stage Q (hi/lo) into smem, then ldmatrix to registers ----
    {
        const __nv_bfloat16* Qh = g_qhi + ((size_t)bh * TT + q0) * HS;
        const __nv_bfloat16* Ql = g_qlo + ((size_t)bh * TT + q0) * HS;
        #pragma unroll
        for (int i = 0; i < 8; i++) {
            int idx = i * 256 + tid;               // 0..2047
            int mtx = idx >> 10;                   // 0 hi, 1 lo
            int r = (idx >> 3) & 127, c8 = idx & 7;
            const __nv_bfloat16* src = (mtx ? Ql : Qh) + r * HS + c8 * 8;
            *(uint4*)(sm + mtx * 18432 + r * 144 + c8 * 16) = *(const uint4*)src;
        }
    }
    __syncthreads();
    uint32_t qh[4][4], ql[4][4];
    #pragma unroll
    for (int kg = 0; kg < 4; kg++) {
        uint32_t a = sb + (uint32_t)(wid * 16 + (lane & 15)) * 144 + kg * 32 + (lane >> 4) * 16;
        ldsm4(qh[kg], a);
        ldsm4(ql[kg], a + 18432);
    }
    __syncthreads();

    // ---- K/V pipeline ----
    auto issueKV = [&](int kt, int s) {
        const uint32_t dstb = sb + s * ASTAGE_B;
        const size_t rowb = ((size_t)bh * TT + kt * 64) * HS;
        #pragma unroll
        for (int i = 0; i < 8; i++) {
            int idx = i * 256 + tid;               // 0..2047
            int mtx = idx >> 9;                    // 0 Khi 1 Klo 2 Vhi 3 Vlo
            int r = (idx >> 3) & 63, c8 = idx & 7;
            const __nv_bfloat16* p =
                (mtx == 0 ? g_khi : mtx == 1 ? g_klo : mtx == 2 ? g_vhi : g_vlo)
                + rowb + r * HS + c8 * 8;
            cp16(dstb + mtx * ATILE_B + r * 144 + c8 * 16, p);
        }
        cp_commit();
    };

    float oacc[8][4];
    #pragma unroll
    for (int nt = 0; nt < 8; nt++)
        #pragma unroll
        for (int c = 0; c < 4; c++) oacc[nt][c] = 0.f;
    float mrow[2] = {-1e30f, -1e30f}, lrow[2] = {0.f, 0.f};

    const int dq = (q0 + wid * 16) >> 6;           // warp's diagonal 64-tile
    const int ktmax = 2 * qt + 1;

    issueKV(0, 0);
    for (int kt = 0; kt <= ktmax; kt++) {
        const int s = kt & 1;
        if (kt < ktmax) { issueKV(kt + 1, s ^ 1); cp_wait<1>(); }
        else            { cp_wait<0>(); }
        __syncthreads();

        if (kt <= dq) {
            const uint32_t base = sb + s * ASTAGE_B;

            // S = Q K^T  (3-term split)
            float sacc[8][4];
            #pragma unroll
            for (int nt = 0; nt < 8; nt++)
                #pragma unroll
                for (int c = 0; c < 4; c++) sacc[nt][c] = 0.f;

            #pragma unroll
            for (int kg = 0; kg < 4; kg++) {
                #pragma unroll
                for (int nt = 0; nt < 8; nt++) {
                    uint32_t ro = base + (uint32_t)(nt * 8 + (lane & 7)) * 144
                                 + kg * 32 + ((lane >> 3) & 1) * 16;
                    uint32_t kbh[2], kbl[2];
                    ldsm2(kbh, ro);
                    ldsm2(kbl, ro + ATILE_B);
                    mma16816(sacc[nt], qh[kg], kbh);
                    mma16816(sacc[nt], ql[kg], kbh);
                    mma16816(sacc[nt], qh[kg], kbl);
                }
            }

            // causal mask on the diagonal tile
            if (kt == dq) {
                const int rl = ((q0 + wid * 16) & 63) + g;
                #pragma unroll
                for (int nt = 0; nt < 8; nt++) {
                    int c0 = nt * 8 + tg * 2;
                    if (c0     > rl)     sacc[nt][0] = -1e30f;
                    if (c0 + 1 > rl)     sacc[nt][1] = -1e30f;
                    if (c0     > rl + 8) sacc[nt][2] = -1e30f;
                    if (c0 + 1 > rl + 8) sacc[nt][3] = -1e30f;
                }
            }

            // online softmax (rows g, g+8; quad reduction over tg)
            #pragma unroll
            for (int r = 0; r < 2; r++) {
                float mx = -1e30f;
                #pragma unroll
                for (int nt = 0; nt < 8; nt++)
                    mx = fmaxf(mx, fmaxf(sacc[nt][2*r], sacc[nt][2*r+1]));
                mx = fmaxf(mx, __shfl_xor_sync(0xffffffffu, mx, 1));
                mx = fmaxf(mx, __shfl_xor_sync(0xffffffffu, mx, 2));
                float mnew = fmaxf(mrow[r], mx);
                float corr = __expf(mrow[r] - mnew);
                float rs = 0.f;
                #pragma unroll
                for (int nt = 0; nt < 8; nt++) {
                    float p0 = __expf(sacc[nt][2*r]   - mnew);
                    float p1 = __expf(sacc[nt][2*r+1] - mnew);
                    sacc[nt][2*r] = p0; sacc[nt][2*r+1] = p1;
                    rs += p0 + p1;
                }
                rs += __shfl_xor_sync(0xffffffffu, rs, 1);
                rs += __shfl_xor_sync(0xffffffffu, rs, 2);
                lrow[r] = lrow[r] * corr + rs;
                mrow[r] = mnew;
                #pragma unroll
                for (int nt = 0; nt < 8; nt++) {
                    oacc[nt][2*r] *= corr; oacc[nt][2*r+1] *= corr;
                }
            }

            // O += P V  (P hi/lo from S fragments; V via ldmatrix.trans)
            #pragma unroll
            for (int kg = 0; kg < 4; kg++) {
                uint32_t ph[4], pl[4];
                #pragma unroll
                for (int q = 0; q < 4; q++) {
                    float a = sacc[2*kg + (q >> 1)][(q & 1) * 2];
                    float b = sacc[2*kg + (q >> 1)][(q & 1) * 2 + 1];
                    ph[q] = packbf2(a, b);
                    __nv_bfloat162 hh = *(__nv_bfloat162*)&ph[q];
                    pl[q] = packbf2(a - __bfloat162float(hh.x),
                                    b - __bfloat162float(hh.y));
                }
                #pragma unroll
                for (int nt = 0; nt < 8; nt++) {
                    uint32_t ro = base + 2 * ATILE_B
                                 + (uint32_t)(kg * 16 + (lane & 15)) * 144 + nt * 16;
                    uint32_t vbh[2], vbl[2];
                    ldsm2t(vbh, ro);
                    ldsm2t(vbl, ro + ATILE_B);
                    mma16816(oacc[nt], ph, vbh);
                    mma16816(oacc[nt], pl, vbh);
                    mma16816(oacc[nt], ph, vbl);
                }
            }
        }
        __syncthreads();
    }

    // epilogue: write hi/lo bf16 directly as the proj-GEMM A operand
    const int b = bh >> 4, h = bh & 15;
    #pragma unroll
    for (int r = 0; r < 2; r++) {
        float inv = 1.0f / lrow[r];
        int t = q0 + wid * 16 + g + r * 8;
        size_t rowo = ((size_t)(b * TT + t)) * EMB + h * HS;
        #pragma unroll
        for (int nt = 0; nt < 8; nt++) {
            float o0 = oacc[nt][2*r] * inv, o1 = oacc[nt][2*r+1] * inv;
            __nv_bfloat16 h0 = __float2bfloat16(o0), h1 = __float2bfloat16(o1);
            __nv_bfloat162 hi2; hi2.x = h0; hi2.y = h1;
            __nv_bfloat162 lo2;
            lo2.x = __float2bfloat16(o0 - __bfloat162float(h0));
            lo2.y = __float2bfloat16(o1 - __bfloat162float(h1));
            size_t o = (rowo + nt * 8 + tg * 2) >> 1;
            ((__nv_bfloat162*)g_ahi)[o] = hi2;
            ((__nv_bfloat162*)g_alo)[o] = lo2;
        }
    }
}

// ---------------------------------------------------------------------------
extern "C" void kernel_launch(void* const* d_in, const int* in_sizes, int n_in,
                              void* d_out, int out_size)
{
    const float* x      = (const float*)d_in[0];
    const float* w_qkv  = (const float*)d_in[1];
    const float* w_proj = (const float*)d_in[2];
    const float* b_proj = (const float*)d_in[3];
    float* out = (float*)d_out;

    cudaFuncSetAttribute(attn_mma, cudaFuncAttributeMaxDynamicSharedMemorySize, ATT_SMEM);
    cudaFuncSetAttribute(mma_gemm<0>, cudaFuncAttributeMaxDynamicSharedMemorySize, GEMM_SMEM);
    cudaFuncSetAttribute(mma_gemm<1>, cudaFuncAttributeMaxDynamicSharedMemorySize, GEMM_SMEM);

    __nv_bfloat16 *xhi, *xlo, *ahi, *alo, *wqhi, *wqlo, *wphi, *wplo;
    cudaGetSymbolAddress((void**)&xhi,  g_xhi);
    cudaGetSymbolAddress((void**)&xlo,  g_xlo);
    cudaGetSymbolAddress((void**)&ahi,  g_ahi);
    cudaGetSymbolAddress((void**)&alo,  g_alo);
    cudaGetSymbolAddress((void**)&wqhi, g_wqhi);
    cudaGetSymbolAddress((void**)&wqlo, g_wqlo);
    cudaGetSymbolAddress((void**)&wphi, g_wphi);
    cudaGetSymbolAddress((void**)&wplo, g_wplo);

    // 1. split x -> bf16 hi/lo
    split_fp32<<<(NROWS * GK / 4 + 255) / 256, 256>>>(
        (const float4*)x, (__nv_bfloat162*)xhi, (__nv_bfloat162*)xlo, NROWS * GK / 4);

    // 2. transpose+split weights
    tsplit_w<<<dim3(3 * EMB / 32, GK / 32), dim3(32, 8)>>>(w_qkv, wqhi, wqlo, 3 * EMB);
    tsplit_w<<<dim3(EMB / 32, GK / 32), dim3(32, 8)>>>(w_proj, wphi, wplo, EMB);

    // 3. QKV GEMM (HMMA) -> bf16 hi/lo q/k/v (Q pre-scaled)
    mma_gemm<0><<<dim3(3 * EMB / 128, NROWS / 128), 256, GEMM_SMEM>>>(
        xhi, xlo, wqhi, wqlo, nullptr, nullptr);

    // 4. tensor-core causal flash attention -> g_ahi/g_alo
    attn_mma<<<dim3(TT / 128, BB * HEADS), 256, ATT_SMEM>>>();

    // 5. output projection (HMMA) + bias
    mma_gemm<1><<<dim3(EMB / 128, NROWS / 128), 256, GEMM_SMEM>>>(
        ahi, alo, wphi, wplo, b_proj, out);
}